// round 6
// baseline (speedup 1.0000x reference)
#include <cuda_runtime.h>
#include <cuda_fp16.h>
#include <mma.h>
#include <math.h>

using namespace nvcuda;

// Problem constants
#define BATCH 4
#define AC 32
#define BC 32
#define PS 16
#define KK 9
#define KKA 288
#define H 14
#define OH 7
#define L 49
#define BL 196
#define NPP 3136
#define NPAD 3200
#define GM 4608          // 16 * 288 fused GEMM M
#define EPSV 1e-12f
#define LN2PI 1.8378770664093453f

// ---------------- device scratch ----------------
__device__ float g_h[16][KKA];
__device__ float g_S[16];
__device__ __half g_Ch[GM][KKA];        // fp16 circulant correction rows (p*288+k)
__device__ float g_PU[KKA][NPAD];       // fp32 unfolded pose
__device__ __half g_PUh[KKA][NPAD];     // fp16 copy for GEMM
__device__ float g_U[16][KKA][NPAD];    // fp32 correction C@PU
__device__ float g_v[BL][KKA][BC][PS];  // votes, fp32 (115.6 MB)
__device__ float g_au[BL][KKA];
__device__ float g_pass0[BL][2][512];   // pass-0 stats: [0]=sum au*v, [1]=sum au*v^2

__device__ __forceinline__ void cp16(void* smem_dst, const void* gsrc) {
    unsigned s = (unsigned)__cvta_generic_to_shared(smem_dst);
    asm volatile("cp.async.cg.shared.global [%0], [%1], 16;\n" :: "r"(s), "l"(gsrc));
}
#define CP_COMMIT() asm volatile("cp.async.commit_group;\n")
#define CP_WAIT(n)  asm volatile("cp.async.wait_group %0;\n" :: "n"(n))

// ---------------- kernel 0: circulant kernels h_p, S_p ----------------
__global__ void k_build_h(const float* __restrict__ fw) {
    int p = blockIdx.x;          // 0..15
    int d = threadIdx.x;         // 0..287
    float wr0   = fw[(0 * 16 + p) * 2];
    float wr144 = fw[(144 * 16 + p) * 2];
    float s = 0.f;
    for (int k = 1; k <= 143; ++k) {
        float wr = fw[(k * 16 + p) * 2];
        float wi = fw[(k * 16 + p) * 2 + 1];
        int md = (k * d) % KKA;
        float x = (float)md * (1.0f / 144.0f);
        float sn, cs;
        sincospif(x, &sn, &cs);
        s += wr * cs - wi * sn;
    }
    float h = (wr0 + ((d & 1) ? -wr144 : wr144) + 2.f * s) * (1.0f / (float)KKA);
    g_h[p][d] = h;
    __shared__ float red[KKA];
    red[d] = h;
    __syncthreads();
    if (d == 0) {
        float t = 0.f;
        for (int i = 0; i < KKA; ++i) t += red[i];
        g_S[p] = t;
    }
}

// ---------------- kernel 1: C rows (p*288+k) fp16; zero pass-0 scratch ----------
__global__ void k_build_C() {
    int idx = blockIdx.x * blockDim.x + threadIdx.x;
    if (idx < BL * 2 * 512) ((float*)g_pass0)[idx] = 0.f;
    if (idx >= 16 * KKA * KKA) return;
    int p = idx / (KKA * KKA);
    int rem = idx - p * KKA * KKA;
    int k = rem / KKA;
    int m = rem - k * KKA;
    int d = k - m; if (d < 0) d += KKA;
    g_Ch[p * KKA + k][m] = __float2half(g_h[p][d]);
}

// ---------------- kernel 2: smem-tiled unfold: block = (batch, a) ----------------
__global__ void k_unfold(const float* __restrict__ pose, const float* __restrict__ a_in) {
    const int blk = blockIdx.x;          // 0..127
    const int batch = blk >> 5;
    const int a = blk & 31;
    const int tid = threadIdx.x;         // 256
    __shared__ float tile[16][197];
    __shared__ float ta[196];

    const float* src = pose + (size_t)(batch * (AC * PS) + a * PS) * 196;
    for (int i = tid; i < 16 * 196; i += 256) {
        int pp = i / 196, r = i - pp * 196;
        tile[pp][r] = src[pp * 196 + r];
    }
    for (int i = tid; i < 196; i += 256)
        ta[i] = a_in[(batch * AC + a) * 196 + i];
    __syncthreads();

    for (int i = tid; i < 9 * 49 * 16; i += 256) {
        int pp = i & 15;
        int rest = i >> 4;               // 0..440
        int pos = rest % 49;
        int kk = rest / 49;
        int y = pos / 7, x = pos - y * 7;
        int iy = 2 * y - 1 + kk / 3;
        int ix = 2 * x - 1 + (kk - (kk / 3) * 3);
        bool ok = (iy >= 0) & (iy < H) & (ix >= 0) & (ix < H);
        float v = ok ? tile[pp][iy * 14 + ix] : 0.f;
        int m = kk * 32 + a;
        int col = (batch * 49 + pos) * 16 + pp;
        g_PU[m][col] = v;
        g_PUh[m][col] = __float2half(v);
        if (pp == 0)
            g_au[batch * 49 + pos][m] = ok ? ta[iy * 14 + ix] : 0.f;
    }
}

// ---------------- kernel 3: fp16 tensor GEMM  U = C(4608x288) @ PUh(288x3200) ----
#define LDA 40
#define LDB 72
__global__ void k_gemm() {
    __shared__ __half sA[2][128 * LDA];
    __shared__ __half sB[2][32 * LDB];
    const int tid = threadIdx.x;
    const int row0 = blockIdx.y * 128;
    const int col0 = blockIdx.x * 64;
    const __half* Ag = &g_Ch[0][0];
    const __half* Bg = &g_PUh[0][0];
    const int wm = (tid >> 5) & 3;
    const int wn = tid >> 7;

    wmma::fragment<wmma::accumulator, 16, 16, 16, float> acc[2][2];
#pragma unroll
    for (int i = 0; i < 2; ++i)
#pragma unroll
        for (int j = 0; j < 2; ++j) wmma::fill_fragment(acc[i][j], 0.f);

    {
#pragma unroll
        for (int t = tid; t < 512; t += 256) {
            int r = t >> 2, c = t & 3;
            cp16(&sA[0][r * LDA + c * 8], Ag + (row0 + r) * KKA + c * 8);
        }
        int r = tid >> 3, c = tid & 7;
        cp16(&sB[0][r * LDB + c * 8], Bg + r * NPAD + col0 + c * 8);
        CP_COMMIT();
    }
    int cur = 0;
    for (int kt = 0; kt < 9; ++kt) {
        if (kt < 8) {
            int k0 = (kt + 1) * 32;
            int nxt = cur ^ 1;
#pragma unroll
            for (int t = tid; t < 512; t += 256) {
                int r = t >> 2, c = t & 3;
                cp16(&sA[nxt][r * LDA + c * 8], Ag + (row0 + r) * KKA + k0 + c * 8);
            }
            int r = tid >> 3, c = tid & 7;
            cp16(&sB[nxt][r * LDB + c * 8], Bg + (k0 + r) * NPAD + col0 + c * 8);
            CP_COMMIT();
            CP_WAIT(1);
        } else {
            CP_WAIT(0);
        }
        __syncthreads();
#pragma unroll
        for (int ks = 0; ks < 2; ++ks) {
            wmma::fragment<wmma::matrix_a, 16, 16, 16, __half, wmma::row_major> a0, a1;
            wmma::fragment<wmma::matrix_b, 16, 16, 16, __half, wmma::row_major> b0, b1;
            wmma::load_matrix_sync(a0, &sA[cur][(wm * 32) * LDA + ks * 16], LDA);
            wmma::load_matrix_sync(a1, &sA[cur][(wm * 32 + 16) * LDA + ks * 16], LDA);
            wmma::load_matrix_sync(b0, &sB[cur][(ks * 16) * LDB + wn * 32], LDB);
            wmma::load_matrix_sync(b1, &sB[cur][(ks * 16) * LDB + wn * 32 + 16], LDB);
            wmma::mma_sync(acc[0][0], a0, b0, acc[0][0]);
            wmma::mma_sync(acc[0][1], a0, b1, acc[0][1]);
            wmma::mma_sync(acc[1][0], a1, b0, acc[1][0]);
            wmma::mma_sync(acc[1][1], a1, b1, acc[1][1]);
        }
        __syncthreads();
        cur ^= 1;
    }
    float* Uf = &g_U[0][0][0];
#pragma unroll
    for (int i = 0; i < 2; ++i)
#pragma unroll
        for (int j = 0; j < 2; ++j)
            wmma::store_matrix_sync(Uf + (size_t)(row0 + wm * 32 + i * 16) * NPAD
                                       + col0 + wn * 32 + j * 16,
                                    acc[i][j], NPAD, wmma::mem_row_major);
}

// ---------------- kernel 4: votes (fp32) + EM pass-0 stats, grid (196, 9) ------
__global__ void k_votes(const float* __restrict__ W, const float* __restrict__ mb) {
    const int bl = blockIdx.x;
    const int k0 = blockIdx.y * 32;
    const int tid = threadIdx.x;      // 512
    __shared__ __align__(16) float Usf[32][16][20];
    __shared__ float sau[32];

    float wreg[16];
    const float4* wv = (const float4*)(W + tid * 16);
#pragma unroll
    for (int f = 0; f < 4; ++f) {
        float4 w4 = wv[f];
        wreg[f * 4 + 0] = w4.x; wreg[f * 4 + 1] = w4.y;
        wreg[f * 4 + 2] = w4.z; wreg[f * 4 + 3] = w4.w;
    }
    if (tid < 32) sau[tid] = g_au[bl][k0 + tid];
    const int b = tid >> 4, p = tid & 15;
    const float sbv = mb[tid] * (1.f + g_S[p]);
    const int col = bl * PS;

    for (int i = tid; i < 2048; i += 512) {
        int f = i & 3;
        int pf = (i >> 2) & 15;
        int k = i >> 6;
        float4 u4 = *(const float4*)&g_U[pf][k0 + k][col + f * 4];
        float4 r4 = *(const float4*)&g_PU[k0 + k][col + f * 4];
        float4 y;
        y.x = u4.x + r4.x; y.y = u4.y + r4.y;
        y.z = u4.z + r4.z; y.w = u4.w + r4.w;
        *(float4*)&Usf[k][pf][f * 4] = y;
    }
    __syncthreads();
    float aV = 0.f, aQ = 0.f;
#pragma unroll 4
    for (int k = 0; k < 32; ++k) {
        const float4* yr = (const float4*)&Usf[k][p][0];
        float4 y0 = yr[0], y1 = yr[1], y2 = yr[2], y3 = yr[3];
        float s = sbv;
        s += y0.x * wreg[0]  + y0.y * wreg[1]  + y0.z * wreg[2]  + y0.w * wreg[3];
        s += y1.x * wreg[4]  + y1.y * wreg[5]  + y1.z * wreg[6]  + y1.w * wreg[7];
        s += y2.x * wreg[8]  + y2.y * wreg[9]  + y2.z * wreg[10] + y2.w * wreg[11];
        s += y3.x * wreg[12] + y3.y * wreg[13] + y3.z * wreg[14] + y3.w * wreg[15];
        g_v[bl][k0 + k][b][p] = s;
        float auk = sau[k];
        aV += auk * s;
        aQ += auk * s * s;
    }
    atomicAdd(&g_pass0[bl][0][tid], aV);
    atomicAdd(&g_pass0[bl][1][tid], aQ);
}

// ---------------- kernel 5: fused EM routing, 2 v-passes ----------------
__global__ void k_em(const float* __restrict__ beta_u, const float* __restrict__ beta_a,
                     float* __restrict__ out) {
    const int bl = blockIdx.x;        // 196
    const int tid = threadIdx.x;      // 512
    const int warp = tid >> 5, lane = tid & 31;
    __shared__ float au[KKA];
    __shared__ float accv[32][17], acc2[32][17];
    __shared__ float accr[32];
    __shared__ float mu[32][17], i2s[32][17], sigs[32][17];
    __shared__ float lsum2[32], loga[32], aouts[32], rsum_sh[32];
    __shared__ float wred[16];
    __shared__ float sau_sh;

    for (int i = tid; i < KKA; i += 512) au[i] = g_au[bl][i];
    __syncthreads();
    {
        float s = (tid < KKA) ? au[tid] : 0.f;
#pragma unroll
        for (int o = 16; o; o >>= 1) s += __shfl_xor_sync(~0u, s, o);
        if (lane == 0) wred[warp] = s;
        __syncthreads();
        if (tid == 0) { float t = 0.f; for (int i = 0; i < 16; ++i) t += wred[i]; sau_sh = t; }
        __syncthreads();
    }
    const float* __restrict__ vb = &g_v[bl][0][0][0];
    const int b = tid >> 4, q = tid & 15;
    const float LOG_LN2PI = logf(LN2PI);

    // ---- finalize iter 0 from votes-kernel stats (uniform r) ----
    {
        float rs = sau_sh * (1.f / 32.f);
        float iv = 1.f / (rs + EPSV);
        float sv = g_pass0[bl][0][tid];
        float sq = g_pass0[bl][1][tid];
        float m  = sv * (1.f / 32.f) * iv;
        float sg = sq * (1.f / 32.f) * iv - m * m + EPSV;
        mu[b][q] = m; sigs[b][q] = sg; i2s[b][q] = 0.5f / sg;
        if (tid < 32) rsum_sh[tid] = rs;
    }
    __syncthreads();
    if (tid < 32) {
        float ls = 0.f;
#pragma unroll
        for (int j = 0; j < 16; ++j) ls += logf(sigs[tid][j]);
        float cost = rsum_sh[tid] * (16.f * beta_u[tid] + 0.5f * ls);
        float z = 5.0e-4f * (beta_a[tid] - cost);
        float ao = 1.f / (1.f + expf(-z));
        aouts[tid] = ao; loga[tid] = logf(ao);
        lsum2[tid] = ls + 16.f * LOG_LN2PI;
    }
    __syncthreads();

    // ---- fused passes: e-step(it) + stats(it+1), it = 0, 1 ----
#pragma unroll 1
    for (int it = 0; it < 2; ++it) {
        for (int i = tid; i < 32 * 17; i += 512) { (&accv[0][0])[i] = 0.f; (&acc2[0][0])[i] = 0.f; }
        if (tid < 32) accr[tid] = 0.f;
        __syncthreads();
        // per-thread cached e-step coefficients (lane = b fixed)
        float A[16], TMA[16];            // A_j = i2s, TMA_j = 2*mu*i2s
        float Kc;
        {
            float cst = 0.f;
#pragma unroll
            for (int j = 0; j < 16; ++j) {
                float m = mu[lane][j], ai = i2s[lane][j];
                A[j] = ai; TMA[j] = 2.f * m * ai;
                cst += m * m * ai;
            }
            Kc = loga[lane] - 0.5f * lsum2[lane] - cst;
        }
        float av[16], a2[16], ar = 0.f;
#pragma unroll
        for (int j = 0; j < 16; ++j) { av[j] = 0.f; a2[j] = 0.f; }
#pragma unroll 2
        for (int k = warp; k < KKA; k += 16) {
            const float4* vp = (const float4*)(vb + (k * 32 + lane) * 16);
            float4 q0 = vp[0], q1 = vp[1], q2 = vp[2], q3 = vp[3];
            float vv[16];
            vv[0]=q0.x; vv[1]=q0.y; vv[2]=q0.z; vv[3]=q0.w;
            vv[4]=q1.x; vv[5]=q1.y; vv[6]=q1.z; vv[7]=q1.w;
            vv[8]=q2.x; vv[9]=q2.y; vv[10]=q2.z; vv[11]=q2.w;
            vv[12]=q3.x; vv[13]=q3.y; vv[14]=q3.z; vv[15]=q3.w;
            float lnap = Kc;
#pragma unroll
            for (int j = 0; j < 16; ++j) {
                float t = fmaf(-A[j], vv[j], TMA[j]);   // 2muA - A*v
                lnap = fmaf(vv[j], t, lnap);            // += v*(2muA - A*v)
            }
            float mx = lnap;
#pragma unroll
            for (int o = 16; o; o >>= 1) mx = fmaxf(mx, __shfl_xor_sync(~0u, mx, o));
            float e = __expf(lnap - mx);
            float se = e;
#pragma unroll
            for (int o = 16; o; o >>= 1) se += __shfl_xor_sync(~0u, se, o);
            float c = (e / se) * au[k];
            ar += c;
#pragma unroll
            for (int j = 0; j < 16; ++j) {
                float t2 = c * vv[j];
                av[j] += t2;
                a2[j] = fmaf(t2, vv[j], a2[j]);
            }
        }
#pragma unroll
        for (int j = 0; j < 16; ++j) {
            atomicAdd(&accv[lane][j], av[j]);
            atomicAdd(&acc2[lane][j], a2[j]);
        }
        atomicAdd(&accr[lane], ar);
        __syncthreads();
        // finalize iter it+1
        {
            float rs = accr[b];
            float iv = 1.f / (rs + EPSV);
            float m  = accv[b][q] * iv;
            float sg = acc2[b][q] * iv - m * m + EPSV;
            mu[b][q] = m; sigs[b][q] = sg; i2s[b][q] = 0.5f / sg;
            if (tid < 32) rsum_sh[tid] = accr[tid];
        }
        __syncthreads();
        if (tid < 32) {
            float ls = 0.f;
#pragma unroll
            for (int j = 0; j < 16; ++j) ls += logf(sigs[tid][j]);
            float cost = rsum_sh[tid] * (16.f * beta_u[tid] + 0.5f * ls);
            float lam = (it == 0) ? 9.75e-4f : 1.42625e-3f;
            float z = lam * (beta_a[tid] - cost);
            float ao = 1.f / (1.f + expf(-z));
            aouts[tid] = ao; loga[tid] = logf(ao);
            lsum2[tid] = ls + 16.f * LOG_LN2PI;
        }
        __syncthreads();
    }
    // outputs: a_fin [BATCH][32][7][7] then pose_out [BATCH][512][7][7]
    int batch = bl / L, pos = bl - batch * L;
    if (tid < 32) out[(batch * 32 + tid) * L + pos] = aouts[tid];
    out[BATCH * 32 * L + (batch * 512 + tid) * L + pos] = mu[b][q];
}

// ---------------- launch ----------------
extern "C" void kernel_launch(void* const* d_in, const int* in_sizes, int n_in,
                              void* d_out, int out_size) {
    const float* a_in   = (const float*)d_in[0];
    const float* pose   = (const float*)d_in[1];
    const float* mposew = (const float*)d_in[2];
    const float* mposeb = (const float*)d_in[3];
    const float* freqw  = (const float*)d_in[4];
    const float* beta_u = (const float*)d_in[9];
    const float* beta_a = (const float*)d_in[10];
    float* out = (float*)d_out;

    k_build_h<<<16, KKA>>>(freqw);
    k_build_C<<<(16 * KKA * KKA + 255) / 256, 256>>>();
    k_unfold<<<128, 256>>>(pose, a_in);
    k_gemm<<<dim3(NPAD / 64, GM / 128), 256>>>();
    k_votes<<<dim3(BL, 9), 512>>>(mposew, mposeb);
    k_em<<<BL, 512>>>(beta_u, beta_a, out);
}